// round 1
// baseline (speedup 1.0000x reference)
#include <cuda_runtime.h>
#include <math.h>

#define N      512
#define LOGN   9
#define NBATCH 16
#define NT     8
#define ROWS_PER_BLK 8     // rows per block in kernel 1
#define PAD    513         // smem row stride (bank-conflict avoidance)

// Scratch (allocation-free rule: __device__ globals)
// Row-FFT result stored TRANSPOSED: layout [b][kx][y], complex
__device__ float2 g_rowfft[(size_t)NBATCH * N * N];
__device__ float  g_segsum[256];

// ---------------------------------------------------------------------------
// K0: zero the radial bins (graph replays must start clean)
// ---------------------------------------------------------------------------
__global__ void kZero() {
    g_segsum[threadIdx.x] = 0.0f;
}

// ---------------------------------------------------------------------------
// K1: mean over T + 512-pt row FFT (radix-2 DIT, smem) + transposed write
// grid = NBATCH * (N / ROWS_PER_BLK) blocks, 512 threads
// ---------------------------------------------------------------------------
__global__ void __launch_bounds__(512) kMeanRowFFT(const float* __restrict__ in) {
    const int tid = threadIdx.x;                 // 0..511 (= column x for loads)
    const int b   = blockIdx.x >> 6;             // / (N/ROWS_PER_BLK)=64
    const int y0  = (blockIdx.x & 63) << 3;      // * ROWS_PER_BLK

    __shared__ float s_re[ROWS_PER_BLK * PAD];
    __shared__ float s_im[ROWS_PER_BLK * PAD];
    __shared__ float tw_re[N / 2];
    __shared__ float tw_im[N / 2];

    if (tid < N / 2) {
        float ang = -6.283185307179586f * (float)tid / (float)N;
        float s, c;
        sincosf(ang, &s, &c);
        tw_re[tid] = c;
        tw_im[tid] = s;
    }

    // mean over T for 8 rows, column tid  (fully coalesced)
    float acc[ROWS_PER_BLK];
#pragma unroll
    for (int k = 0; k < ROWS_PER_BLK; k++) acc[k] = 0.0f;

    const float* base = in + ((size_t)b * NT) * N * N + (size_t)y0 * N + tid;
#pragma unroll
    for (int t = 0; t < NT; t++) {
        const float* p = base + (size_t)t * N * N;
#pragma unroll
        for (int k = 0; k < ROWS_PER_BLK; k++) acc[k] += p[k * N];
    }

    // store at bit-reversed positions (real input, imag = 0)
    const int rx = __brev((unsigned)tid) >> (32 - LOGN);
#pragma unroll
    for (int k = 0; k < ROWS_PER_BLK; k++) {
        s_re[k * PAD + rx] = acc[k] * 0.125f;
        s_im[k * PAD + rx] = 0.0f;
    }
    __syncthreads();

    // 9 radix-2 DIT stages; 8 rows * 256 butterflies = 2048 -> 4 per thread
    for (int s = 1; s <= LOGN; s++) {
        const int half  = 1 << (s - 1);
        const int tstep = N >> s;
#pragma unroll
        for (int u = 0; u < 4; u++) {
            int idx = tid + u * 512;
            int row = idx >> 8;
            int t   = idx & 255;
            int pos = t & (half - 1);
            int i0  = ((t >> (s - 1)) << s) + pos;
            int i1  = i0 + half;
            float wr = tw_re[pos * tstep];
            float wi = tw_im[pos * tstep];
            float* rre = s_re + row * PAD;
            float* rim = s_im + row * PAD;
            float ar = rre[i0], ai = rim[i0];
            float br = rre[i1], bi = rim[i1];
            float tr = br * wr - bi * wi;
            float ti = br * wi + bi * wr;
            rre[i0] = ar + tr; rim[i0] = ai + ti;
            rre[i1] = ar - tr; rim[i1] = ai - ti;
        }
        __syncthreads();
    }

    // transposed write: g_rowfft[b][kx][y0+yl]; warp covers 4 kx * 8 y -> 64B runs
    const int yl  = tid & 7;
    const int kx0 = tid >> 3;          // 0..63
    float2* outp = g_rowfft + (size_t)b * N * N;
#pragma unroll
    for (int chunk = 0; chunk < 8; chunk++) {
        int kx = kx0 + chunk * 64;
        float2 v = make_float2(s_re[yl * PAD + kx], s_im[yl * PAD + kx]);
        outp[(size_t)kx * N + y0 + yl] = v;
    }
}

// ---------------------------------------------------------------------------
// K2: per-kx column FFT (complex), accumulate |F|^2 over batches, radial bins
// grid = N blocks (one per kx), 256 threads
// ---------------------------------------------------------------------------
__global__ void __launch_bounds__(256) kColFFTPower() {
    const int tid = threadIdx.x;      // 0..255
    const int kx  = blockIdx.x;       // 0..511

    __shared__ float s_re[N];
    __shared__ float s_im[N];
    __shared__ float accum[N];
    __shared__ float tw_re[N / 2];
    __shared__ float tw_im[N / 2];
    __shared__ float bins[256];

    {
        float ang = -6.283185307179586f * (float)tid / (float)N;
        float s, c;
        sincosf(ang, &s, &c);
        tw_re[tid] = c;
        tw_im[tid] = s;
        bins[tid]  = 0.0f;
    }
    accum[tid]       = 0.0f;
    accum[tid + 256] = 0.0f;

    const int r0 = __brev((unsigned)tid) >> (32 - LOGN);
    const int r1 = __brev((unsigned)(tid + 256)) >> (32 - LOGN);

    for (int b = 0; b < NBATCH; b++) {
        const float2* p = g_rowfft + ((size_t)b * N + kx) * N;
        float2 v0 = p[tid];
        float2 v1 = p[tid + 256];
        __syncthreads();                 // previous accum reads done
        s_re[r0] = v0.x; s_im[r0] = v0.y;
        s_re[r1] = v1.x; s_im[r1] = v1.y;
        __syncthreads();

        for (int s = 1; s <= LOGN; s++) {
            const int half  = 1 << (s - 1);
            const int tstep = N >> s;
            int t   = tid;
            int pos = t & (half - 1);
            int i0  = ((t >> (s - 1)) << s) + pos;
            int i1  = i0 + half;
            float wr = tw_re[pos * tstep];
            float wi = tw_im[pos * tstep];
            float ar = s_re[i0], ai = s_im[i0];
            float br = s_re[i1], bi = s_im[i1];
            float tr = br * wr - bi * wi;
            float ti = br * wi + bi * wr;
            s_re[i0] = ar + tr; s_im[i0] = ai + ti;
            s_re[i1] = ar - tr; s_im[i1] = ai - ti;
            __syncthreads();
        }
        accum[tid]       += s_re[tid] * s_re[tid] + s_im[tid] * s_im[tid];
        accum[tid + 256] += s_re[tid + 256] * s_re[tid + 256] +
                            s_im[tid + 256] * s_im[tid + 256];
    }
    __syncthreads();

    // radial binning (match jnp: int cast of fp32 sqrt, unshifted indices)
    const int   dx   = kx - 256;
    const float fdx2 = (float)(dx * dx);
#pragma unroll
    for (int ky = tid; ky < N; ky += 256) {
        int dy = ky - 256;
        int r  = (int)sqrtf(fdx2 + (float)(dy * dy));
        if (r >= 1 && r < 256) atomicAdd(&bins[r], accum[ky]);
    }
    __syncthreads();

    if (tid >= 1 && bins[tid] != 0.0f) atomicAdd(&g_segsum[tid], bins[tid]);
}

// ---------------------------------------------------------------------------
// K3: counts + normalization + loss (single block)
// ---------------------------------------------------------------------------
__global__ void __launch_bounds__(256) kFinal(float* __restrict__ out) {
    __shared__ float cnt[256];
    __shared__ float red[256];
    __shared__ float gsum_s, rsum_s;
    const int tid = threadIdx.x;

    cnt[tid] = 0.0f;
    __syncthreads();

    for (int i = tid; i < N; i += 256) {
        int dy = i - 256;
        float fdy2 = (float)(dy * dy);
        for (int j = 0; j < N; j++) {
            int dx = j - 256;
            int r  = (int)sqrtf(fdy2 + (float)(dx * dx));
            if (r < 256) atomicAdd(&cnt[r], 1.0f);
        }
    }
    __syncthreads();

    float g = 0.0f, rk = 0.0f;
    if (tid >= 1) {
        float c = cnt[tid];
        if (c > 0.0f) g = g_segsum[tid] / (fmaxf(c, 1.0f) * 16.0f);  // B*C = 16
        rk = powf((float)tid, -5.0f / 3.0f);
    }

    red[tid] = g;
    __syncthreads();
    for (int s = 128; s > 0; s >>= 1) { if (tid < s) red[tid] += red[tid + s]; __syncthreads(); }
    if (tid == 0) gsum_s = red[0];
    __syncthreads();

    red[tid] = rk;
    __syncthreads();
    for (int s = 128; s > 0; s >>= 1) { if (tid < s) red[tid] += red[tid + s]; __syncthreads(); }
    if (tid == 0) rsum_s = red[0];
    __syncthreads();

    float gn = g  / (gsum_s + 1e-8f);
    float rn = rk / (rsum_s + 1e-8f);
    float d  = (tid >= 1) ? (gn - rn) * (gn - rn) : 0.0f;

    red[tid] = d;
    __syncthreads();
    for (int s = 128; s > 0; s >>= 1) { if (tid < s) red[tid] += red[tid + s]; __syncthreads(); }
    if (tid == 0) out[0] = red[0] / 255.0f;
}

// ---------------------------------------------------------------------------
extern "C" void kernel_launch(void* const* d_in, const int* in_sizes, int n_in,
                              void* d_out, int out_size) {
    const float* in  = (const float*)d_in[0];
    float*       out = (float*)d_out;

    kZero<<<1, 256>>>();
    kMeanRowFFT<<<NBATCH * (N / ROWS_PER_BLK), 512>>>(in);
    kColFFTPower<<<N, 256>>>();
    kFinal<<<1, 256>>>(out);
}

// round 2
// speedup vs baseline: 3.9564x; 3.9564x over previous
#include <cuda_runtime.h>
#include <math.h>

#define N      512
#define LOGN   9
#define NBATCH 16
#define NT     8
#define ROWS_PER_BLK 8     // rows per block in kernel 1
#define PAD    513         // smem row stride (bank-conflict avoidance)

// Scratch (allocation-free rule: __device__ globals)
// Row-FFT result stored TRANSPOSED: layout [b][kx][y], complex
__device__ float2 g_rowfft[(size_t)NBATCH * N * N];
__device__ float  g_segsum[256];
__device__ float  g_cnt[256];

// ---------------------------------------------------------------------------
// K0: zero the radial bins (graph replays must start clean)
// ---------------------------------------------------------------------------
__global__ void kZero() {
    g_segsum[threadIdx.x] = 0.0f;
    g_cnt[threadIdx.x]    = 0.0f;
}

// ---------------------------------------------------------------------------
// K1: mean over T + 512-pt row FFT (radix-2 DIT, smem) + transposed write
// grid = NBATCH * (N / ROWS_PER_BLK) blocks, 512 threads
// ---------------------------------------------------------------------------
__global__ void __launch_bounds__(512) kMeanRowFFT(const float* __restrict__ in) {
    const int tid = threadIdx.x;                 // 0..511 (= column x for loads)
    const int b   = blockIdx.x >> 6;             // / (N/ROWS_PER_BLK)=64
    const int y0  = (blockIdx.x & 63) << 3;      // * ROWS_PER_BLK

    __shared__ float s_re[ROWS_PER_BLK * PAD];
    __shared__ float s_im[ROWS_PER_BLK * PAD];
    __shared__ float tw_re[N / 2];
    __shared__ float tw_im[N / 2];

    if (tid < N / 2) {
        float ang = -6.283185307179586f * (float)tid / (float)N;
        float s, c;
        sincosf(ang, &s, &c);
        tw_re[tid] = c;
        tw_im[tid] = s;
    }

    // mean over T for 8 rows, column tid  (fully coalesced)
    float acc[ROWS_PER_BLK];
#pragma unroll
    for (int k = 0; k < ROWS_PER_BLK; k++) acc[k] = 0.0f;

    const float* base = in + ((size_t)b * NT) * N * N + (size_t)y0 * N + tid;
#pragma unroll
    for (int t = 0; t < NT; t++) {
        const float* p = base + (size_t)t * N * N;
#pragma unroll
        for (int k = 0; k < ROWS_PER_BLK; k++) acc[k] += p[k * N];
    }

    // store at bit-reversed positions (real input, imag = 0)
    const int rx = __brev((unsigned)tid) >> (32 - LOGN);
#pragma unroll
    for (int k = 0; k < ROWS_PER_BLK; k++) {
        s_re[k * PAD + rx] = acc[k] * 0.125f;
        s_im[k * PAD + rx] = 0.0f;
    }
    __syncthreads();

    // 9 radix-2 DIT stages; 8 rows * 256 butterflies = 2048 -> 4 per thread
    for (int s = 1; s <= LOGN; s++) {
        const int half  = 1 << (s - 1);
        const int tstep = N >> s;
#pragma unroll
        for (int u = 0; u < 4; u++) {
            int idx = tid + u * 512;
            int row = idx >> 8;
            int t   = idx & 255;
            int pos = t & (half - 1);
            int i0  = ((t >> (s - 1)) << s) + pos;
            int i1  = i0 + half;
            float wr = tw_re[pos * tstep];
            float wi = tw_im[pos * tstep];
            float* rre = s_re + row * PAD;
            float* rim = s_im + row * PAD;
            float ar = rre[i0], ai = rim[i0];
            float br = rre[i1], bi = rim[i1];
            float tr = br * wr - bi * wi;
            float ti = br * wi + bi * wr;
            rre[i0] = ar + tr; rim[i0] = ai + ti;
            rre[i1] = ar - tr; rim[i1] = ai - ti;
        }
        __syncthreads();
    }

    // transposed write: g_rowfft[b][kx][y0+yl]; warp covers 4 kx * 8 y -> 64B runs
    const int yl  = tid & 7;
    const int kx0 = tid >> 3;          // 0..63
    float2* outp = g_rowfft + (size_t)b * N * N;
#pragma unroll
    for (int chunk = 0; chunk < 8; chunk++) {
        int kx = kx0 + chunk * 64;
        float2 v = make_float2(s_re[yl * PAD + kx], s_im[yl * PAD + kx]);
        outp[(size_t)kx * N + y0 + yl] = v;
    }
}

// ---------------------------------------------------------------------------
// K2: per-kx column FFT (complex), accumulate |F|^2 over batches, radial bins
//     ALSO accumulates the radial counts histogram (this kx's ky-sweep)
// grid = N blocks (one per kx), 256 threads
// ---------------------------------------------------------------------------
__global__ void __launch_bounds__(256) kColFFTPower() {
    const int tid = threadIdx.x;      // 0..255
    const int kx  = blockIdx.x;       // 0..511

    __shared__ float s_re[N];
    __shared__ float s_im[N];
    __shared__ float accum[N];
    __shared__ float tw_re[N / 2];
    __shared__ float tw_im[N / 2];
    __shared__ float bins[256];
    __shared__ float cbin[256];

    {
        float ang = -6.283185307179586f * (float)tid / (float)N;
        float s, c;
        sincosf(ang, &s, &c);
        tw_re[tid] = c;
        tw_im[tid] = s;
        bins[tid]  = 0.0f;
        cbin[tid]  = 0.0f;
    }
    accum[tid]       = 0.0f;
    accum[tid + 256] = 0.0f;

    const int r0 = __brev((unsigned)tid) >> (32 - LOGN);
    const int r1 = __brev((unsigned)(tid + 256)) >> (32 - LOGN);

    for (int b = 0; b < NBATCH; b++) {
        const float2* p = g_rowfft + ((size_t)b * N + kx) * N;
        float2 v0 = p[tid];
        float2 v1 = p[tid + 256];
        __syncthreads();                 // previous accum reads done
        s_re[r0] = v0.x; s_im[r0] = v0.y;
        s_re[r1] = v1.x; s_im[r1] = v1.y;
        __syncthreads();

        for (int s = 1; s <= LOGN; s++) {
            const int half  = 1 << (s - 1);
            const int tstep = N >> s;
            int t   = tid;
            int pos = t & (half - 1);
            int i0  = ((t >> (s - 1)) << s) + pos;
            int i1  = i0 + half;
            float wr = tw_re[pos * tstep];
            float wi = tw_im[pos * tstep];
            float ar = s_re[i0], ai = s_im[i0];
            float br = s_re[i1], bi = s_im[i1];
            float tr = br * wr - bi * wi;
            float ti = br * wi + bi * wr;
            s_re[i0] = ar + tr; s_im[i0] = ai + ti;
            s_re[i1] = ar - tr; s_im[i1] = ai - ti;
            __syncthreads();
        }
        accum[tid]       += s_re[tid] * s_re[tid] + s_im[tid] * s_im[tid];
        accum[tid + 256] += s_re[tid + 256] * s_re[tid + 256] +
                            s_im[tid + 256] * s_im[tid + 256];
    }
    __syncthreads();

    // radial binning (match jnp: int cast of fp32 sqrt, unshifted indices)
    // + counts: this block covers exactly the (kx, ky=0..511) strip of the grid
    const int   dx   = kx - 256;
    const float fdx2 = (float)(dx * dx);
#pragma unroll
    for (int ky = tid; ky < N; ky += 256) {
        int dy = ky - 256;
        int r  = (int)sqrtf(fdx2 + (float)(dy * dy));
        if (r >= 1 && r < 256) {
            atomicAdd(&bins[r], accum[ky]);
            atomicAdd(&cbin[r], 1.0f);
        }
    }
    __syncthreads();

    if (tid >= 1) {
        if (bins[tid] != 0.0f) atomicAdd(&g_segsum[tid], bins[tid]);
        if (cbin[tid] != 0.0f) atomicAdd(&g_cnt[tid],    cbin[tid]);
    }
}

// ---------------------------------------------------------------------------
// K3: normalization + loss (single block, counts precomputed by K2)
// ---------------------------------------------------------------------------
__global__ void __launch_bounds__(256) kFinal(float* __restrict__ out) {
    __shared__ float red[256];
    __shared__ float gsum_s, rsum_s;
    const int tid = threadIdx.x;

    float g = 0.0f, rk = 0.0f;
    if (tid >= 1) {
        float c = g_cnt[tid];
        if (c > 0.0f) g = g_segsum[tid] / (fmaxf(c, 1.0f) * 16.0f);  // B*C = 16
        rk = powf((float)tid, -5.0f / 3.0f);
    }

    red[tid] = g;
    __syncthreads();
    for (int s = 128; s > 0; s >>= 1) { if (tid < s) red[tid] += red[tid + s]; __syncthreads(); }
    if (tid == 0) gsum_s = red[0];
    __syncthreads();

    red[tid] = rk;
    __syncthreads();
    for (int s = 128; s > 0; s >>= 1) { if (tid < s) red[tid] += red[tid + s]; __syncthreads(); }
    if (tid == 0) rsum_s = red[0];
    __syncthreads();

    float gn = g  / (gsum_s + 1e-8f);
    float rn = rk / (rsum_s + 1e-8f);
    float d  = (tid >= 1) ? (gn - rn) * (gn - rn) : 0.0f;

    red[tid] = d;
    __syncthreads();
    for (int s = 128; s > 0; s >>= 1) { if (tid < s) red[tid] += red[tid + s]; __syncthreads(); }
    if (tid == 0) out[0] = red[0] / 255.0f;
}

// ---------------------------------------------------------------------------
extern "C" void kernel_launch(void* const* d_in, const int* in_sizes, int n_in,
                              void* d_out, int out_size) {
    const float* in  = (const float*)d_in[0];
    float*       out = (float*)d_out;

    kZero<<<1, 256>>>();
    kMeanRowFFT<<<NBATCH * (N / ROWS_PER_BLK), 512>>>(in);
    kColFFTPower<<<N, 256>>>();
    kFinal<<<1, 256>>>(out);
}

// round 3
// speedup vs baseline: 11.3298x; 2.8637x over previous
#include <cuda_runtime.h>
#include <math.h>

#define N       512
#define NBATCH  16
#define NT      8
#define NKX     257            // kx = 0..256 kept (Hermitian symmetry)

// Scratch: row-FFT result, TRANSPOSED + half-spectrum: [b][kx][y], kx<257
__device__ float2 g_rowfft[(size_t)NBATCH * NKX * N];
__device__ float  g_segsum[256];
__device__ float  g_cnt[256];

// ---------------------------------------------------------------------------
// complex helpers
// ---------------------------------------------------------------------------
__device__ __forceinline__ float2 cadd(float2 a, float2 b){ return make_float2(a.x+b.x, a.y+b.y); }
__device__ __forceinline__ float2 csub(float2 a, float2 b){ return make_float2(a.x-b.x, a.y-b.y); }
__device__ __forceinline__ float2 cmul(float2 a, float2 b){ return make_float2(a.x*b.x-a.y*b.y, a.x*b.y+a.y*b.x); }
__device__ __forceinline__ float2 mul_mi(float2 a){ return make_float2(a.y, -a.x); }   // * (-i)

// 8-point DFT, natural order in/out, forward (e^{-2pi i/8})
__device__ __forceinline__ void fft8(float2 v[8]) {
    float2 t0, t1, t2, t3, t3m;
    // DFT4 on evens
    t0 = cadd(v[0], v[4]); t1 = csub(v[0], v[4]);
    t2 = cadd(v[2], v[6]); t3 = csub(v[2], v[6]);
    float2 E0 = cadd(t0, t2), E2 = csub(t0, t2);
    t3m = mul_mi(t3);
    float2 E1 = cadd(t1, t3m), E3 = csub(t1, t3m);
    // DFT4 on odds
    t0 = cadd(v[1], v[5]); t1 = csub(v[1], v[5]);
    t2 = cadd(v[3], v[7]); t3 = csub(v[3], v[7]);
    float2 O0 = cadd(t0, t2), O2 = csub(t0, t2);
    t3m = mul_mi(t3);
    float2 O1 = cadd(t1, t3m), O3 = csub(t1, t3m);
    // twiddles w8^k
    const float C = 0.7071067811865476f;
    float2 O1w = make_float2(C*(O1.x + O1.y), C*(O1.y - O1.x));   // *(c - ci)
    float2 O2w = mul_mi(O2);                                       // *(-i)
    float2 O3w = make_float2(C*(O3.y - O3.x), -C*(O3.x + O3.y));   // *(-c - ci)
    v[0] = cadd(E0, O0);  v[4] = csub(E0, O0);
    v[1] = cadd(E1, O1w); v[5] = csub(E1, O1w);
    v[2] = cadd(E2, O2w); v[6] = csub(E2, O2w);
    v[3] = cadd(E3, O3w); v[7] = csub(E3, O3w);
}

// ---------------------------------------------------------------------------
// 512-pt FFT, 64 threads (gt = 0..63), 8 elems/thread, radix-8^3 DIF.
// Input: v[j] = x[gt + 64*j]. Output: thread (m=gt>>3, u=gt&7) holds
// X[64*s + 8*u + m] in v[s].  gre/gim: 512-float staging (per group).
// Twiddle: tre/tim[k] = e^{-2pi i k/512}.
// Caller provides syncthreads alignment across groups (all groups lockstep).
// ---------------------------------------------------------------------------
__device__ __forceinline__ void fft512(float2 v[8], int gt,
                                       float* __restrict__ gre, float* __restrict__ gim,
                                       const float* __restrict__ tre, const float* __restrict__ tim) {
    // Stage A: 8-pt DFT over j, twiddle w512^(n0*m), n0 = gt
    fft8(v);
#pragma unroll
    for (int m = 1; m < 8; m++) {
        int k = gt * m;                       // <= 441
        v[m] = cmul(v[m], make_float2(tre[k], tim[k]));
    }
#pragma unroll
    for (int m = 0; m < 8; m++) {
        int idx = m * 64 + (gt ^ (m << 3));
        gre[idx] = v[m].x; gim[idx] = v[m].y;
    }
    __syncthreads();
    // Stage B: thread (m, p)
    {
        int m = gt >> 3, p = gt & 7;
#pragma unroll
        for (int i = 0; i < 8; i++) {
            int idx = m * 64 + p + (((i ^ m) & 7) << 3);
            v[i] = make_float2(gre[idx], gim[idx]);
        }
        fft8(v);                               // over i -> index u
#pragma unroll
        for (int u = 1; u < 8; u++) {
            int k = (p * u) << 3;              // 8*p*u <= 392
            v[u] = cmul(v[u], make_float2(tre[k], tim[k]));
        }
        __syncthreads();                       // WAR on staging
#pragma unroll
        for (int u = 0; u < 8; u++) {
            int idx = m * 64 + (((u ^ m) & 7) << 3) + (p ^ (u & 3));
            gre[idx] = v[u].x; gim[idx] = v[u].y;
        }
    }
    __syncthreads();
    // Stage C: thread (m, u)
    {
        int m = gt >> 3, u = gt & 7;
#pragma unroll
        for (int p = 0; p < 8; p++) {
            int idx = m * 64 + (((u ^ m) & 7) << 3) + (p ^ (u & 3));
            v[p] = make_float2(gre[idx], gim[idx]);
        }
        fft8(v);                               // over p -> index s; X[64s+8u+m] = v[s]
    }
}

// ---------------------------------------------------------------------------
// K1: mean over T + row FFT (radix-8), write transposed half-spectrum
// grid = NBATCH * 64 blocks, 512 threads (8 rows x 64)
// ---------------------------------------------------------------------------
__global__ void __launch_bounds__(512) kMeanRowFFT(const float* __restrict__ in) {
    const int tid = threadIdx.x;
    const int r   = tid >> 6;          // row in block (0..7)
    const int gt  = tid & 63;          // thread in FFT group
    const int b   = blockIdx.x >> 6;
    const int y0  = (blockIdx.x & 63) << 3;

    __shared__ float sre[8 * 512];
    __shared__ float sim[8 * 512];
    __shared__ float tre[512];
    __shared__ float tim[512];

    {
        float s, c;
        sincosf(-6.283185307179586f * (float)tid / 512.0f, &s, &c);
        tre[tid] = c; tim[tid] = s;
    }
    if (blockIdx.x == 0 && tid < 256) { g_segsum[tid] = 0.0f; g_cnt[tid] = 0.0f; }

    // mean over T: v[j] = mean_t in[b][t][y0+r][gt+64j]
    float2 v[8];
    const float* base = in + (((size_t)b * NT) * N + (y0 + r)) * N + gt;
#pragma unroll
    for (int j = 0; j < 8; j++) {
        float s = 0.0f;
#pragma unroll
        for (int t = 0; t < NT; t++) s += base[(size_t)t * N * N + (j << 6)];
        v[j] = make_float2(s * 0.125f, 0.0f);
    }
    __syncthreads();   // twiddle table ready

    float* gre = sre + r * 512;
    float* gim = sim + r * 512;
    fft512(v, gt, gre, gim, tre, tim);

    __syncthreads();   // stage-C reads done; reuse buffers for transpose
    // restage: sre[kx*8 + (r^u)] , u = (kx>>3)&7
    {
        int m = gt >> 3, u = gt & 7;
#pragma unroll
        for (int s = 0; s < 8; s++) {
            int kx  = (s << 6) + (u << 3) + m;
            int idx = (kx << 3) + (r ^ u);
            sre[idx] = v[s].x; sim[idx] = v[s].y;
        }
    }
    __syncthreads();

    // global write, kx = 0..256 only (Hermitian half)
    const int yl  = tid & 7;
    const int kxi = tid >> 3;          // 0..63
    float2* outp = g_rowfft + (size_t)b * NKX * N + y0 + yl;
#pragma unroll
    for (int c5 = 0; c5 < 5; c5++) {
        int kx = kxi + (c5 << 6);
        if (kx <= 256) {
            int uu  = (kx >> 3) & 7;
            int idx = (kx << 3) + (yl ^ uu);
            outp[(size_t)kx * N] = make_float2(sre[idx], sim[idx]);
        }
    }
}

// ---------------------------------------------------------------------------
// K2: column FFT per kx (4 batch-groups of 64 threads), |F|^2 in registers,
//     radial binning with Hermitian weight. grid = 257, 256 threads.
// ---------------------------------------------------------------------------
__global__ void __launch_bounds__(256) kColFFTPower() {
    const int tid = threadIdx.x;
    const int g   = tid >> 6;          // batch group 0..3
    const int gt  = tid & 63;
    const int kx  = blockIdx.x;        // 0..256

    __shared__ float sre[4 * 512];
    __shared__ float sim[4 * 512];
    __shared__ float tre[512];
    __shared__ float tim[512];
    __shared__ float bins[256];
    __shared__ float cbin[256];

    {
        float s, c;
        sincosf(-6.283185307179586f * (float)tid / 512.0f, &s, &c);
        tre[tid] = c; tim[tid] = s;
        sincosf(-6.283185307179586f * (float)(tid + 256) / 512.0f, &s, &c);
        tre[tid + 256] = c; tim[tid + 256] = s;
        bins[tid] = 0.0f; cbin[tid] = 0.0f;
    }
    __syncthreads();

    float* gre = sre + g * 512;
    float* gim = sim + g * 512;
    float pw[8];
#pragma unroll
    for (int s = 0; s < 8; s++) pw[s] = 0.0f;

    for (int it = 0; it < 4; it++) {
        const int b = g + (it << 2);
        const float2* col = g_rowfft + ((size_t)b * NKX + kx) * N;
        float2 v[8];
#pragma unroll
        for (int j = 0; j < 8; j++) v[j] = col[gt + (j << 6)];

        fft512(v, gt, gre, gim, tre, tim);

#pragma unroll
        for (int s = 0; s < 8; s++) pw[s] += v[s].x * v[s].x + v[s].y * v[s].y;
        __syncthreads();   // buffer reuse next round
    }

    // radial binning: thread (m,u) owns ky = 64s+8u+m
    {
        const float w    = (kx == 0 || kx == 256) ? 1.0f : 2.0f;
        const float fdx2 = (float)((kx - 256) * (kx - 256));
        int m = gt >> 3, u = gt & 7;
#pragma unroll
        for (int s = 0; s < 8; s++) {
            int ky = (s << 6) + (u << 3) + m;
            int dy = ky - 256;
            int rr = (int)sqrtf(fdx2 + (float)(dy * dy));
            if (rr >= 1 && rr < 256) {
                atomicAdd(&bins[rr], w * pw[s]);
                if (g == 0) atomicAdd(&cbin[rr], w);
            }
        }
    }
    __syncthreads();

    if (tid >= 1) {
        if (bins[tid] != 0.0f) atomicAdd(&g_segsum[tid], bins[tid]);
        if (cbin[tid] != 0.0f) atomicAdd(&g_cnt[tid],    cbin[tid]);
    }
}

// ---------------------------------------------------------------------------
// K3: normalization + loss (single block)
// ---------------------------------------------------------------------------
__global__ void __launch_bounds__(256) kFinal(float* __restrict__ out) {
    __shared__ float red[256];
    __shared__ float gsum_s, rsum_s;
    const int tid = threadIdx.x;

    float g = 0.0f, rk = 0.0f;
    if (tid >= 1) {
        float c = g_cnt[tid];
        if (c > 0.0f) g = g_segsum[tid] / (fmaxf(c, 1.0f) * 16.0f);  // B*C
        rk = __powf((float)tid, -5.0f / 3.0f);
    }

    red[tid] = g;
    __syncthreads();
    for (int s = 128; s > 0; s >>= 1) { if (tid < s) red[tid] += red[tid + s]; __syncthreads(); }
    if (tid == 0) gsum_s = red[0];
    __syncthreads();

    red[tid] = rk;
    __syncthreads();
    for (int s = 128; s > 0; s >>= 1) { if (tid < s) red[tid] += red[tid + s]; __syncthreads(); }
    if (tid == 0) rsum_s = red[0];
    __syncthreads();

    float gn = g  / (gsum_s + 1e-8f);
    float rn = rk / (rsum_s + 1e-8f);
    float d  = (tid >= 1) ? (gn - rn) * (gn - rn) : 0.0f;

    red[tid] = d;
    __syncthreads();
    for (int s = 128; s > 0; s >>= 1) { if (tid < s) red[tid] += red[tid + s]; __syncthreads(); }
    if (tid == 0) out[0] = red[0] / 255.0f;
}

// ---------------------------------------------------------------------------
extern "C" void kernel_launch(void* const* d_in, const int* in_sizes, int n_in,
                              void* d_out, int out_size) {
    const float* in  = (const float*)d_in[0];
    float*       out = (float*)d_out;

    kMeanRowFFT<<<NBATCH * (N / 8), 512>>>(in);
    kColFFTPower<<<NKX, 256>>>();
    kFinal<<<1, 256>>>(out);
}